// round 16
// baseline (speedup 1.0000x reference)
#include <cuda_runtime.h>
#include <cuda_fp16.h>
#include <cstdint>

// Problem constants
#define BB 2
#define SS 2048
#define DD 2048
#define HH 32
#define HD 64
#define MM (BB * SS)          // 4096 rows

// ---------------------------------------------------------------------------
// Device scratch (allocation is banned -> device globals)
// ---------------------------------------------------------------------------
__device__ __half g_qkv16[(size_t)3 * MM * DD];   // q,k,v fp16 HEAD-MAJOR [z][b,h,s,d]
__device__ __half g_h16[(size_t)MM * DD];         // hidden fp16
__device__ __half g_attn16[(size_t)MM * DD];      // attention out fp16 [b,s,h*d]
__device__ __half g_W16[(size_t)4 * DD * DD];     // W fp16 K-MAJOR [z][k][n], z=0..2 qkv, 3 o
__device__ float2 g_rtab[(size_t)BB * SS * 32];   // (cos, sin) per (b,s,i)

// ---------------------------------------------------------------------------
// Portable PTX helpers (valid on .target sm_103 WITHOUT the 'a' suffix)
// ---------------------------------------------------------------------------
__device__ __forceinline__ uint32_t smem_to_u32(const void* p) {
    uint32_t a;
    asm("{ .reg .u64 t; cvta.to.shared.u64 t, %1; cvt.u32.u64 %0, t; }" : "=r"(a) : "l"(p));
    return a;
}

#define SW128(off) ((off) ^ (((off) >> 3) & 0x70))

#define CP_ASYNC16(dst_u32, src_ptr) \
    asm volatile("cp.async.cg.shared.global [%0], [%1], 16;" \
                 :: "r"(dst_u32), "l"(src_ptr) : "memory")
#define CP_COMMIT()  asm volatile("cp.async.commit_group;" ::: "memory")
#define CP_WAIT_1()  asm volatile("cp.async.wait_group 1;" ::: "memory")
#define CP_WAIT_0()  asm volatile("cp.async.wait_group 0;" ::: "memory")

__device__ __forceinline__ void ldm_x4(uint32_t* r, uint32_t addr) {
    asm volatile("ldmatrix.sync.aligned.m8n8.x4.shared.b16 {%0,%1,%2,%3}, [%4];"
                 : "=r"(r[0]), "=r"(r[1]), "=r"(r[2]), "=r"(r[3]) : "r"(addr));
}
__device__ __forceinline__ void ldm_x4_t(uint32_t* r, uint32_t addr) {
    asm volatile("ldmatrix.sync.aligned.m8n8.x4.trans.shared.b16 {%0,%1,%2,%3}, [%4];"
                 : "=r"(r[0]), "=r"(r[1]), "=r"(r[2]), "=r"(r[3]) : "r"(addr));
}
__device__ __forceinline__ void mma_f16(float* d, const uint32_t* a, const uint32_t* b) {
    asm volatile(
        "mma.sync.aligned.m16n8k16.row.col.f32.f16.f16.f32 "
        "{%0,%1,%2,%3}, {%4,%5,%6,%7}, {%8,%9}, {%0,%1,%2,%3};"
        : "+f"(d[0]), "+f"(d[1]), "+f"(d[2]), "+f"(d[3])
        : "r"(a[0]), "r"(a[1]), "r"(a[2]), "r"(a[3]), "r"(b[0]), "r"(b[1]));
}
__device__ __forceinline__ uint32_t pack_h2(float x, float y) {
    __half2 h = __floats2half2_rn(x, y);
    return *(uint32_t*)&h;
}
__device__ __forceinline__ uint32_t ex2_h2(uint32_t x) {
    uint32_t r;
    asm("ex2.approx.f16x2 %0, %1;" : "=r"(r) : "r"(x));
    return r;
}
__device__ __forceinline__ float2 h2_to_f2(uint32_t h) {
    __half2 v = *(__half2*)&h;
    return __half22float2(v);
}

// ---------------------------------------------------------------------------
// Conversion kernel (elementwise, coalesced both sides)
// ---------------------------------------------------------------------------
__global__ void f32_to_f16_kernel(const float* __restrict__ x, __half* __restrict__ y)
{
    const size_t i = (size_t)blockIdx.x * blockDim.x + threadIdx.x; // per float2
    float2 v = ((const float2*)x)[i];
    ((__half2*)y)[i] = __floats2half2_rn(v.x, v.y);
}

// ---------------------------------------------------------------------------
// fp16 single-pass mma.sync GEMM, 128x128 CTA tile, WARP TILE 64x64.
// 128 threads = 4 warps in 2(m) x 2(n). Cuts LDSM bytes/MMA by 1/3 vs 64x32
// (per ks: 4 A-ldm + 4 B-ldm serve 32 MMAs). Reg cap 256 @ 2 CTAs/SM.
// C[z](M x N) = A(M x K) * W[z](K x N) + bias[z] (+ add)
// A: fp16 [M,K] row-major (.row, ldmatrix). W: fp16 [z][K,N] K-major,
// B fragments via ldmatrix.trans (.col) -- addressing proven in R14.
// F16OUT: fp16 output written HEAD-MAJOR [z][b,h,s,d]; else fp32 (+ add).
// ---------------------------------------------------------------------------
#define BKC      64
#define NCHUNK   (DD / BKC)          // 32
#define GSTAGE   32768               // A 16KB + B 16KB
#define GOFF_B   16384
#define GEMM_SMEM (3 * GSTAGE)       // 98304

template <bool F16OUT>
__global__ __launch_bounds__(128, 2)
void gemm_f16_kernel(const __half* __restrict__ A,
                     const __half* __restrict__ W,       // [z][K][N]
                     const float* __restrict__ biasBase, // [z][N]
                     const float* __restrict__ add,      // nullptr or [M][N] (fp32 out only)
                     void* __restrict__ Cbase)           // [z][...]
{
    extern __shared__ char smem[];
    const uint32_t smem_u = smem_to_u32(smem);

    const int tid  = threadIdx.x;
    const int wid  = tid >> 5;
    const int lane = tid & 31;
    const int wm   = wid & 1;        // m-half (64 rows)
    const int wn   = wid >> 1;       // n-half (64 cols)

    const int z    = blockIdx.z;
    const int col0 = blockIdx.x * 128;
    const int row0 = blockIdx.y * 128;

    const __half* B = W + (size_t)z * DD * DD;
    const float* bias = biasBase + (size_t)z * DD;

    // ---- ldmatrix per-lane addressing ----
    const uint32_t swz    = (uint32_t)(lane & 7) * 16;
    const uint32_t aOff   = (uint32_t)(wm * 64 + (lane & 15)) * 128;
    const uint32_t aSub   = (uint32_t)(lane >> 4) * 16;
    const uint32_t krow_l = (uint32_t)(((lane >> 3) & 1) * 8 + (lane & 7));
    const uint32_t bg_hi  = (uint32_t)(lane >> 4);
    const uint32_t bHB    = (uint32_t)wn * 8192;          // n half-block base

    float acc[4][8][4];
#pragma unroll
    for (int i = 0; i < 4; i++)
#pragma unroll
        for (int j = 0; j < 8; j++)
#pragma unroll
            for (int u = 0; u < 4; u++) acc[i][j][u] = 0.f;

    // ---- loaders: 1024 granules per operand, 8/thread (recompute offsets) ----
    // A granule e: row = e>>3, g = e&7 -> smem SW128(row*128 + g*16)
    // B granule e: k = e>>4, gn = e&15, hb = gn>>3, g = gn&7
    //              -> smem GOFF_B + hb*8192 + SW128(k*128 + g*16)
#define GEMM_LOAD_STAGE(sb, k0)                                                          \
    do {                                                                                 \
        _Pragma("unroll")                                                                \
        for (int it = 0; it < 8; it++) {                                                 \
            const int e = tid + it * 128;                                                \
            const int ar = e >> 3, ag = e & 7;                                           \
            CP_ASYNC16((sb) + SW128((uint32_t)(ar * 128 + ag * 16)),                     \
                       A + (size_t)(row0 + ar) * DD + (k0) + ag * 8);                    \
            const int bk = e >> 4, gn = e & 15, hb = gn >> 3, bg = gn & 7;               \
            CP_ASYNC16((sb) + GOFF_B + (uint32_t)hb * 8192 +                             \
                           SW128((uint32_t)(bk * 128 + bg * 16)),                       \
                       B + (size_t)((k0) + bk) * DD + col0 + hb * 64 + bg * 8);          \
        }                                                                                \
        CP_COMMIT();                                                                     \
    } while (0)

    // prologue: stages 0,1
    GEMM_LOAD_STAGE(smem_u, 0);
    GEMM_LOAD_STAGE(smem_u + GSTAGE, BKC);

    // mainloop: one barrier per chunk
#pragma unroll 1
    for (int c = 0; c < NCHUNK; c++) {
        if (c < NCHUNK - 2) { CP_WAIT_1(); } else { CP_WAIT_0(); }
        __syncthreads();

        if (c + 2 < NCHUNK) {
            const uint32_t sbn = smem_u + (uint32_t)((c + 2) % 3) * GSTAGE;
            const int k0n = (c + 2) * BKC;
            GEMM_LOAD_STAGE(sbn, k0n);
        }

        const uint32_t sb = smem_u + (uint32_t)(c % 3) * GSTAGE;
#pragma unroll
        for (int ks = 0; ks < 4; ks++) {
            // B fragments for full 64-n warp tile: 4 trans-ldm
            uint32_t bf[4][4];
            const uint32_t krow = (uint32_t)(ks * 16) + krow_l;
#pragma unroll
            for (int p = 0; p < 4; p++) {
                const uint32_t g = (uint32_t)p * 2 + bg_hi;
                ldm_x4_t(bf[p], sb + GOFF_B + bHB + krow * 128 + ((g ^ (krow & 7)) * 16));
            }
            const uint32_t aK = ((uint32_t)(ks * 32) + aSub) ^ swz;
#pragma unroll
            for (int i = 0; i < 4; i++) {
                uint32_t a[4];
                ldm_x4(a, sb + aOff + (uint32_t)i * 2048 + aK);
#pragma unroll
                for (int j = 0; j < 8; j++)
                    mma_f16(acc[i][j], a, &bf[j >> 1][(j & 1) * 2]);
            }
        }
        // no bottom barrier: next iteration's top barrier orders smem reuse
    }

    // epilogue
    const int qrow = lane >> 2;
    const int qcol = (lane & 3) * 2;
#pragma unroll
    for (int i = 0; i < 4; i++) {
        const int r0 = row0 + wm * 64 + i * 16 + qrow;
        const int r1 = r0 + 8;
#pragma unroll
        for (int j = 0; j < 8; j++) {
            const int col = col0 + wn * 64 + j * 8 + qcol;
            float2 bv = *(const float2*)&bias[col];
            float2 v0, v1;
            v0.x = acc[i][j][0] + bv.x;  v0.y = acc[i][j][1] + bv.y;
            v1.x = acc[i][j][2] + bv.x;  v1.y = acc[i][j][3] + bv.y;
            if (F16OUT) {
                __half* C = (__half*)Cbase + (size_t)z * MM * DD;
                const int hh = col >> 6, dd_ = col & 63;
                const size_t d0 = (((size_t)(r0 >> 11) * HH + hh) * SS + (r0 & 2047)) * HD + dd_;
                const size_t d1 = (((size_t)(r1 >> 11) * HH + hh) * SS + (r1 & 2047)) * HD + dd_;
                *(__half2*)&C[d0] = __floats2half2_rn(v0.x, v0.y);
                *(__half2*)&C[d1] = __floats2half2_rn(v1.x, v1.y);
            } else {
                float* C = (float*)Cbase + (size_t)z * MM * DD;
                if (add != nullptr) {
                    float2 a0 = *(const float2*)&add[(size_t)r0 * DD + col];
                    float2 a1 = *(const float2*)&add[(size_t)r1 * DD + col];
                    v0.x += a0.x; v0.y += a0.y;
                    v1.x += a1.x; v1.y += a1.y;
                }
                *(float2*)&C[(size_t)r0 * DD + col] = v0;
                *(float2*)&C[(size_t)r1 * DD + col] = v1;
            }
        }
    }
#undef GEMM_LOAD_STAGE
}

// ---------------------------------------------------------------------------
// RoPE sincos table: tbl[b][s][i] = (cos, sin) of pos_ids[b,s] * inv_freq(i).
// ---------------------------------------------------------------------------
__global__ void rope_tab_kernel(const int* __restrict__ pos_ids,
                                float2* __restrict__ tab)
{
    const int idx = blockIdx.x * blockDim.x + threadIdx.x;  // < BB*SS*32
    const int i = idx & 31;
    const int s = (idx >> 5) & 2047;
    const int b = idx >> 16;

    const float pos = (float)pos_ids[b * SS + s];
    const float inv_freq = exp2f(-(float)i * (13.2877123795494f / 32.0f));
    float c, sn;
    sincosf(pos * inv_freq, &sn, &c);
    tab[idx] = make_float2(c, sn);
}

// ---------------------------------------------------------------------------
// RoPE in-place on q,k (head-major [b,h,s,d] fp16), using the table.
// Q scaled by 0.125 * log2(e) so flash softmax works in exp2 domain.
// ---------------------------------------------------------------------------
#define QSCALE 0.1803368801111244f   // 0.125 * 1.4426950408889634

__global__ void rope_inplace_kernel(__half* __restrict__ q,
                                    __half* __restrict__ k,
                                    const float2* __restrict__ tab)
{
    const size_t idx = (size_t)blockIdx.x * blockDim.x + threadIdx.x; // < B*H*S*32
    const int i = (int)(idx & 31);
    const int s = (int)((idx >> 5) & 2047);
    const int h = (int)((idx >> 16) & 31);
    const int b = (int)(idx >> 21);

    const float2 cs = tab[(((size_t)b * SS + s) << 5) + i];
    const float c = cs.x, sn = cs.y;

    const size_t base = (((size_t)b * HH + h) * SS + s) * HD;

    float q1 = __half2float(q[base + i]), q2 = __half2float(q[base + i + 32]);
    q[base + i]      = __float2half((q1 * c - q2 * sn) * QSCALE);
    q[base + i + 32] = __float2half((q2 * c + q1 * sn) * QSCALE);

    float k1 = __half2float(k[base + i]), k2 = __half2float(k[base + i + 32]);
    k[base + i]      = __float2half(k1 * c - k2 * sn);
    k[base + i + 32] = __float2half(k2 * c + k1 * sn);
}

// ---------------------------------------------------------------------------
// Tensor-core causal flash attention (fp16 mma, fp32 accum, exp2-domain
// online softmax with ex2.approx.f16x2). 64 q-rows x (b,h), 4 warps.
// ---------------------------------------------------------------------------
#define FL_SMEM (5 * 8192)   // Q (8K) + 2 stages x (K 8K + V 8K)

__global__ __launch_bounds__(128)
void flash_mma_kernel(const __half* __restrict__ qg,
                      const __half* __restrict__ kg,
                      const __half* __restrict__ vg,
                      __half* __restrict__ out)
{
    __shared__ __align__(128) char sm[FL_SMEM];
    const uint32_t sQ = smem_to_u32(sm);

    const int b  = blockIdx.z;
    const int h  = blockIdx.y;
    const int q0 = (gridDim.x - 1 - blockIdx.x) * 64;   // big blocks first
    const int tid = threadIdx.x;
    const int wid = tid >> 5;
    const int lane = tid & 31;

    const __half* qptr = qg + (((size_t)b * HH + h) * SS + q0) * HD;
    const __half* kptr = kg + (((size_t)b * HH + h) * SS) * HD;
    const __half* vptr = vg + (((size_t)b * HH + h) * SS) * HD;

#pragma unroll
    for (int it = 0; it < 4; it++) {
        int e = tid + it * 128;
        int r = e >> 3, g = e & 7;
        CP_ASYNC16(sQ + SW128((uint32_t)(r * 128 + g * 16)), (const char*)qptr + e * 16);
    }

    const int ntiles = q0 / 64 + 1;

    {
        const char* ks = (const char*)kptr;
        const char* vs = (const char*)vptr;
        uint32_t base = sQ + 8192;
#pragma unroll
        for (int it = 0; it < 4; it++) {
            int e = tid + it * 128;
            int r = e >> 3, g = e & 7;
            uint32_t d = SW128((uint32_t)(r * 128 + g * 16));
            CP_ASYNC16(base + d, ks + e * 16);
            CP_ASYNC16(base + 8192 + d, vs + e * 16);
        }
        CP_COMMIT();
    }
    if (ntiles > 1) {
        const char* ks = (const char*)(kptr + (size_t)64 * HD);
        const char* vs = (const char*)(vptr + (size_t)64 * HD);
        uint32_t base = sQ + 8192 + 16384;
#pragma unroll
        for (int it = 0; it < 4; it++) {
            int e = tid + it * 128;
            int r = e >> 3, g = e & 7;
            uint32_t d = SW128((uint32_t)(r * 128 + g * 16));
            CP_ASYNC16(base + d, ks + e * 16);
            CP_ASYNC16(base + 8192 + d, vs + e * 16);
        }
        CP_COMMIT();
    }

    const uint32_t swz     = (uint32_t)(lane & 7) * 16;
    const uint32_t qrowoff = (uint32_t)(wid * 16 + (lane & 15)) * 128;
    const uint32_t aSub    = (uint32_t)(lane >> 4) * 16;
    const uint32_t krowoff = (uint32_t)((lane & 7) + ((lane >> 4) ? 8 : 0)) * 128;
    const uint32_t bSub    = (uint32_t)((lane >> 3) & 1) * 16;
    const uint32_t vrow_l  = (uint32_t)(((lane >> 3) & 1) * 8 + (lane & 7));
    const uint32_t vg_hi   = (uint32_t)(lane >> 4);

    float m0 = -1e30f, m1 = -1e30f, l0 = 0.f, l1 = 0.f;
    float o[8][4];
#pragma unroll
    for (int j = 0; j < 8; j++)
#pragma unroll
        for (int u = 0; u < 4; u++) o[j][u] = 0.f;

    const int row_g0 = q0 + wid * 16 + (lane >> 2);
    const int row_g1 = row_g0 + 8;

#pragma unroll 1
    for (int t = 0; t < ntiles; t++) {
        if (t < ntiles - 1) { CP_WAIT_1(); } else { CP_WAIT_0(); }
        __syncthreads();

        const uint32_t kb = sQ + 8192 + (uint32_t)(t & 1) * 16384;
        const uint32_t vb = kb + 8192;

        float s[8][4];
#pragma unroll
        for (int j = 0; j < 8; j++)
#pragma unroll
            for (int u = 0; u < 4; u++) s[j][u] = 0.f;

#pragma unroll
        for (int ks = 0; ks < 4; ks++) {
            uint32_t a[4];
            ldm_x4(a, sQ + qrowoff + (((uint32_t)(ks * 32) + aSub) ^ swz));
#pragma unroll
            for (int nt = 0; nt < 4; nt++) {
                uint32_t bf[4];
                ldm_x4(bf, kb + krowoff + (uint32_t)nt * 2048 +
                            (((uint32_t)(ks * 32) + bSub) ^ swz));
                mma_f16(s[2 * nt],     a, bf);
                mma_f16(s[2 * nt + 1], a, bf + 2);
            }
        }

        if (t == ntiles - 1) {
            const int kbase = t * 64;
#pragma unroll
            for (int j = 0; j < 8; j++) {
                const int col = kbase + j * 8 + (lane & 3) * 2;
                if (col     > row_g0) s[j][0] = -1e30f;
                if (col + 1 > row_g0) s[j][1] = -1e30f;
                if (col     > row_g1) s[j][2] = -1e30f;
                if (col + 1 > row_g1) s[j][3] = -1e30f;
            }
        }

        float x0 = -1e30f, x1 = -1e30f;
#pragma unroll
        for (int j = 0; j < 8; j++) {
            x0 = fmaxf(x0, fmaxf(s[j][0], s[j][1]));
            x1 = fmaxf(x1, fmaxf(s[j][2], s[j][3]));
        }
        x0 = fmaxf(x0, __shfl_xor_sync(0xffffffffu, x0, 1));
        x0 = fmaxf(x0, __shfl_xor_sync(0xffffffffu, x0, 2));
        x1 = fmaxf(x1, __shfl_xor_sync(0xffffffffu, x1, 1));
        x1 = fmaxf(x1, __shfl_xor_sync(0xffffffffu, x1, 2));

        const float mn0 = fmaxf(m0, x0);
        const float mn1 = fmaxf(m1, x1);
        const float a0 = exp2f(m0 - mn0);
        const float a1 = exp2f(m1 - mn1);
        m0 = mn0; m1 = mn1;

        uint32_t pa[4][4];
        float sum0 = 0.f, sum1 = 0.f;
#pragma unroll
        for (int c = 0; c < 4; c++) {
            pa[c][0] = ex2_h2(pack_h2(s[2 * c][0] - mn0,     s[2 * c][1] - mn0));
            pa[c][1] = ex2_h2(pack_h2(s[2 * c][2] - mn1,     s[2 * c][3] - mn1));
            pa[c][2] = ex2_h2(pack_h2(s[2 * c + 1][0] - mn0, s[2 * c + 1][1] - mn0));
            pa[c][3] = ex2_h2(pack_h2(s[2 * c + 1][2] - mn1, s[2 * c + 1][3] - mn1));
            float2 f;
            f = h2_to_f2(pa[c][0]); sum0 += f.x + f.y;
            f = h2_to_f2(pa[c][2]); sum0 += f.x + f.y;
            f = h2_to_f2(pa[c][1]); sum1 += f.x + f.y;
            f = h2_to_f2(pa[c][3]); sum1 += f.x + f.y;
        }
        sum0 += __shfl_xor_sync(0xffffffffu, sum0, 1);
        sum0 += __shfl_xor_sync(0xffffffffu, sum0, 2);
        sum1 += __shfl_xor_sync(0xffffffffu, sum1, 1);
        sum1 += __shfl_xor_sync(0xffffffffu, sum1, 2);
        l0 = l0 * a0 + sum0;
        l1 = l1 * a1 + sum1;

#pragma unroll
        for (int j = 0; j < 8; j++) {
            o[j][0] *= a0; o[j][1] *= a0;
            o[j][2] *= a1; o[j][3] *= a1;
        }

#pragma unroll
        for (int c = 0; c < 4; c++) {
            const uint32_t vrow = (uint32_t)(c * 16) + vrow_l;
#pragma unroll
            for (int nt = 0; nt < 4; nt++) {
                const uint32_t g = (uint32_t)(nt * 2) + vg_hi;
                uint32_t bf[4];
                ldm_x4_t(bf, vb + vrow * 128 + ((g ^ (vrow & 7)) * 16));
                mma_f16(o[2 * nt],     pa[c], bf);
                mma_f16(o[2 * nt + 1], pa[c], bf + 2);
            }
        }

        __syncthreads();

        if (t + 2 < ntiles) {
            const char* ks = (const char*)(kptr + (size_t)(t + 2) * 64 * HD);
            const char* vs = (const char*)(vptr + (size_t)(t + 2) * 64 * HD);
            uint32_t base = sQ + 8192 + (uint32_t)(t & 1) * 16384;
#pragma unroll
            for (int it = 0; it < 4; it++) {
                int e = tid + it * 128;
                int r = e >> 3, g = e & 7;
                uint32_t d = SW128((uint32_t)(r * 128 + g * 16));
                CP_ASYNC16(base + d, ks + e * 16);
                CP_ASYNC16(base + 8192 + d, vs + e * 16);
            }
            CP_COMMIT();
        }
    }

    // write attn out fp16: [b*S + row][h*64 + d]
    const float inv0 = 1.f / l0;
    const float inv1 = 1.f / l1;
    __half* ob = out + ((size_t)b * SS) * DD + h * HD;
#pragma unroll
    for (int j = 0; j < 8; j++) {
        const int col = j * 8 + (lane & 3) * 2;
        *(__half2*)&ob[(size_t)row_g0 * DD + col] = __floats2half2_rn(o[j][0] * inv0, o[j][1] * inv0);
        *(__half2*)&ob[(size_t)row_g1 * DD + col] = __floats2half2_rn(o[j][2] * inv1, o[j][3] * inv1);
    }
}

// ---------------------------------------------------------------------------
// Launch
// ---------------------------------------------------------------------------
extern "C" void kernel_launch(void* const* d_in, const int* in_sizes, int n_in,
                              void* d_out, int out_size)
{
    const float* hidden   = (const float*)d_in[0];
    /* d_in[1] attention_mask: causal tril(0 / -1e9) -> handled analytically */
    const int*   pos_ids  = (const int*)d_in[2];
    const float* qkv_w    = (const float*)d_in[3];
    const float* qkv_b    = (const float*)d_in[4];
    const float* o_w      = (const float*)d_in[5];
    const float* o_b      = (const float*)d_in[6];
    const float* residual = (const float*)d_in[7];
    float*       out      = (float*)d_out;

    void* p = nullptr;
    cudaGetSymbolAddress(&p, g_qkv16);  __half* qkv16 = (__half*)p;
    cudaGetSymbolAddress(&p, g_h16);    __half* h16 = (__half*)p;
    cudaGetSymbolAddress(&p, g_attn16); __half* attn16 = (__half*)p;
    cudaGetSymbolAddress(&p, g_W16);    __half* W16 = (__half*)p;
    cudaGetSymbolAddress(&p, g_rtab);   float2* rtab = (float2*)p;

    __half* q16 = qkv16;
    __half* k16 = qkv16 + (size_t)MM * DD;
    __half* v16 = qkv16 + (size_t)2 * MM * DD;

    cudaFuncSetAttribute(gemm_f16_kernel<true>,
                         cudaFuncAttributeMaxDynamicSharedMemorySize, GEMM_SMEM);
    cudaFuncSetAttribute(gemm_f16_kernel<false>,
                         cudaFuncAttributeMaxDynamicSharedMemorySize, GEMM_SMEM);

    // 0) Elementwise fp32->fp16 conversions + rope table
    {
        size_t n2 = (size_t)MM * DD / 2;
        f32_to_f16_kernel<<<(unsigned)(n2 / 256), 256>>>(hidden, h16);
        size_t w2 = (size_t)3 * DD * DD / 2;
        f32_to_f16_kernel<<<(unsigned)(w2 / 256), 256>>>(qkv_w, W16);
        size_t o2 = (size_t)DD * DD / 2;
        f32_to_f16_kernel<<<(unsigned)(o2 / 256), 256>>>(o_w, W16 + (size_t)3 * DD * DD);
        rope_tab_kernel<<<(BB * SS * 32) / 256, 256>>>(pos_ids, rtab);
    }

    // 1) QKV projection -> fp16 head-major [z][b,h,s,d] (bias fused)
    {
        dim3 grid(DD / 128, MM / 128, 3);
        gemm_f16_kernel<true><<<grid, 128, GEMM_SMEM>>>(h16, W16, qkv_b, nullptr, qkv16);
    }

    // 2) RoPE in-place on q,k via table (q pre-scaled into exp2 domain)
    {
        size_t total = (size_t)BB * HH * SS * 32;
        rope_inplace_kernel<<<(unsigned)(total / 256), 256>>>(q16, k16, rtab);
    }

    // 3) Tensor-core causal flash attention -> attn16 (fp16)
    {
        dim3 grid(SS / 64, HH, BB);
        flash_mma_kernel<<<grid, 128>>>(q16, k16, v16, attn16);
    }

    // 4) O-projection + bias + residual -> d_out (fp32)
    {
        dim3 grid(DD / 128, MM / 128, 1);
        gemm_f16_kernel<false><<<grid, 128, GEMM_SMEM>>>(attn16, W16 + (size_t)3 * DD * DD,
                                                         o_b, residual, out);
    }
}

// round 17
// speedup vs baseline: 1.0539x; 1.0539x over previous
#include <cuda_runtime.h>
#include <cuda_fp16.h>
#include <cstdint>

// Problem constants
#define BB 2
#define SS 2048
#define DD 2048
#define HH 32
#define HD 64
#define MM (BB * SS)          // 4096 rows

// ---------------------------------------------------------------------------
// Device scratch (allocation is banned -> device globals)
// ---------------------------------------------------------------------------
__device__ __half g_qkv16[(size_t)3 * MM * DD];   // q,k,v fp16 HEAD-MAJOR [z][b,h,s,d]
__device__ __half g_h16[(size_t)MM * DD];         // hidden fp16
__device__ __half g_attn16[(size_t)MM * DD];      // attention out fp16 [b,s,h*d]
__device__ __half g_W16[(size_t)4 * DD * DD];     // W fp16 K-MAJOR [z][k][n], z=0..2 qkv, 3 o
__device__ float2 g_rtab[(size_t)BB * SS * 32];   // (cos, sin) per (b,s,i)

// ---------------------------------------------------------------------------
// Portable PTX helpers (valid on .target sm_103 WITHOUT the 'a' suffix)
// ---------------------------------------------------------------------------
__device__ __forceinline__ uint32_t smem_to_u32(const void* p) {
    uint32_t a;
    asm("{ .reg .u64 t; cvta.to.shared.u64 t, %1; cvt.u32.u64 %0, t; }" : "=r"(a) : "l"(p));
    return a;
}

#define SW128(off) ((off) ^ (((off) >> 3) & 0x70))

#define CP_ASYNC16(dst_u32, src_ptr) \
    asm volatile("cp.async.cg.shared.global [%0], [%1], 16;" \
                 :: "r"(dst_u32), "l"(src_ptr) : "memory")
#define CP_COMMIT()  asm volatile("cp.async.commit_group;" ::: "memory")
#define CP_WAIT_1()  asm volatile("cp.async.wait_group 1;" ::: "memory")
#define CP_WAIT_0()  asm volatile("cp.async.wait_group 0;" ::: "memory")

__device__ __forceinline__ void ldm_x4(uint32_t* r, uint32_t addr) {
    asm volatile("ldmatrix.sync.aligned.m8n8.x4.shared.b16 {%0,%1,%2,%3}, [%4];"
                 : "=r"(r[0]), "=r"(r[1]), "=r"(r[2]), "=r"(r[3]) : "r"(addr));
}
__device__ __forceinline__ void ldm_x4_t(uint32_t* r, uint32_t addr) {
    asm volatile("ldmatrix.sync.aligned.m8n8.x4.trans.shared.b16 {%0,%1,%2,%3}, [%4];"
                 : "=r"(r[0]), "=r"(r[1]), "=r"(r[2]), "=r"(r[3]) : "r"(addr));
}
__device__ __forceinline__ void mma_f16(float* d, const uint32_t* a, const uint32_t* b) {
    asm volatile(
        "mma.sync.aligned.m16n8k16.row.col.f32.f16.f16.f32 "
        "{%0,%1,%2,%3}, {%4,%5,%6,%7}, {%8,%9}, {%0,%1,%2,%3};"
        : "+f"(d[0]), "+f"(d[1]), "+f"(d[2]), "+f"(d[3])
        : "r"(a[0]), "r"(a[1]), "r"(a[2]), "r"(a[3]), "r"(b[0]), "r"(b[1]));
}
__device__ __forceinline__ uint32_t pack_h2(float x, float y) {
    __half2 h = __floats2half2_rn(x, y);
    return *(uint32_t*)&h;
}
__device__ __forceinline__ uint32_t ex2_h2(uint32_t x) {
    uint32_t r;
    asm("ex2.approx.f16x2 %0, %1;" : "=r"(r) : "r"(x));
    return r;
}
__device__ __forceinline__ float2 h2_to_f2(uint32_t h) {
    __half2 v = *(__half2*)&h;
    return __half22float2(v);
}

#define QSCALE 0.1803368801111244f   // 0.125 * log2(e)

// ---------------------------------------------------------------------------
// Conversion kernel (elementwise, coalesced both sides)
// ---------------------------------------------------------------------------
__global__ void f32_to_f16_kernel(const float* __restrict__ x, __half* __restrict__ y)
{
    const size_t i = (size_t)blockIdx.x * blockDim.x + threadIdx.x; // per float2
    float2 v = ((const float2*)x)[i];
    ((__half2*)y)[i] = __floats2half2_rn(v.x, v.y);
}

// ---------------------------------------------------------------------------
// RoPE sincos table: tbl[b][s][i] = (cos, sin) of pos_ids[b,s] * inv_freq(i).
// ---------------------------------------------------------------------------
__global__ void rope_tab_kernel(const int* __restrict__ pos_ids,
                                float2* __restrict__ tab)
{
    const int idx = blockIdx.x * blockDim.x + threadIdx.x;  // < BB*SS*32
    const int i = idx & 31;
    const int s = (idx >> 5) & 2047;
    const int b = idx >> 16;

    const float pos = (float)pos_ids[b * SS + s];
    const float inv_freq = exp2f(-(float)i * (13.2877123795494f / 32.0f));
    float c, sn;
    sincosf(pos * inv_freq, &sn, &c);
    tab[idx] = make_float2(c, sn);
}

// ---------------------------------------------------------------------------
// fp16 single-pass mma.sync GEMM, 128x128 CTA tile (proven 256-thread R14
// geometry: 8 warps, warp tile 64x32). NEW: warp owns n-cols
// {16a..16a+15} U {16a+32..16a+47} of one head (granules 2a,2a+1,2a+4,2a+5),
// so RoPE (d, d+32) pairs live in one thread -> rope fused into epilogue.
// F16OUT: fp16 head-major output [z][b,h,s,d] with RoPE applied to z<2
//         (q also scaled into exp2 domain). else: fp32 row-major (+ add).
// ---------------------------------------------------------------------------
#define BKC      64
#define NCHUNK   (DD / BKC)          // 32
#define GSTAGE   32768               // A 16KB + B 16KB
#define GOFF_B   16384
#define GEMM_SMEM (3 * GSTAGE)       // 98304

template <bool F16OUT>
__global__ __launch_bounds__(256, 2)
void gemm_f16_kernel(const __half* __restrict__ A,
                     const __half* __restrict__ W,       // [z][K][N]
                     const float* __restrict__ biasBase, // [z][N]
                     const float* __restrict__ add,      // nullptr or [M][N] (fp32 out only)
                     const float4* __restrict__ rtab4,   // rope table as float4 (F16OUT only)
                     void* __restrict__ Cbase)           // [z][...]
{
    extern __shared__ char smem[];
    const uint32_t smem_u = smem_to_u32(smem);

    const int tid  = threadIdx.x;
    const int wid  = tid >> 5;
    const int lane = tid & 31;
    const int wm   = wid & 1;        // m-half (64 rows)
    const int wn   = wid >> 1;       // n-quarter
    const int wa   = wn & 1;         // sub-half selector within head

    const int z    = blockIdx.z;
    const int col0 = blockIdx.x * 128;
    const int row0 = blockIdx.y * 128;

    const __half* B = W + (size_t)z * DD * DD;
    const float* bias = biasBase + (size_t)z * DD;

    // ---- loader mappings (4 granules/thread per operand) ----
    uint32_t a_dst[4];
    int a_row[4], a_g[4];
    uint32_t b_dst[4];
    int b_k[4], b_hb[4], b_g[4];
#pragma unroll
    for (int it = 0; it < 4; it++) {
        int e = tid + it * 256;
        a_row[it] = e >> 3; a_g[it] = e & 7;
        a_dst[it] = SW128((uint32_t)(a_row[it] * 128 + a_g[it] * 16));
        b_k[it]  = e >> 4;
        int gn   = e & 15;
        b_hb[it] = gn >> 3;
        b_g[it]  = gn & 7;
        b_dst[it] = GOFF_B + (uint32_t)b_hb[it] * 8192 +
                    SW128((uint32_t)(b_k[it] * 128 + b_g[it] * 16));
    }

    // ---- ldmatrix per-lane addressing ----
    const uint32_t swz    = (uint32_t)(lane & 7) * 16;
    const uint32_t aOff   = (uint32_t)(wm * 64 + (lane & 15)) * 128;
    const uint32_t aSub   = (uint32_t)(lane >> 4) * 16;
    const uint32_t krow_l = (uint32_t)(((lane >> 3) & 1) * 8 + (lane & 7));
    const uint32_t bg_hi  = (uint32_t)(lane >> 4);
    const uint32_t bHB    = (uint32_t)(wn >> 1) * 8192;   // head half-block base
    const uint32_t bGbase = (uint32_t)wa * 2;             // granules 2a +{0,1}, +4{0,1}

    float acc[4][4][4];
#pragma unroll
    for (int i = 0; i < 4; i++)
#pragma unroll
        for (int j = 0; j < 4; j++)
#pragma unroll
            for (int u = 0; u < 4; u++) acc[i][j][u] = 0.f;

    // prologue: stages 0,1
#pragma unroll 1
    for (int c = 0; c < 2; c++) {
        const int k0 = c * BKC;
        const uint32_t sb = smem_u + (uint32_t)c * GSTAGE;
#pragma unroll
        for (int it = 0; it < 4; it++) {
            CP_ASYNC16(sb + a_dst[it], A + (size_t)(row0 + a_row[it]) * DD + k0 + a_g[it] * 8);
            CP_ASYNC16(sb + b_dst[it], B + (size_t)(k0 + b_k[it]) * DD + col0 + b_hb[it] * 64 + b_g[it] * 8);
        }
        CP_COMMIT();
    }

    // mainloop: one barrier per chunk
#pragma unroll 1
    for (int c = 0; c < NCHUNK; c++) {
        if (c < NCHUNK - 2) { CP_WAIT_1(); } else { CP_WAIT_0(); }
        __syncthreads();

        if (c + 2 < NCHUNK) {
            const int k0 = (c + 2) * BKC;
            const uint32_t sb = smem_u + (uint32_t)((c + 2) % 3) * GSTAGE;
#pragma unroll
            for (int it = 0; it < 4; it++) {
                CP_ASYNC16(sb + a_dst[it], A + (size_t)(row0 + a_row[it]) * DD + k0 + a_g[it] * 8);
                CP_ASYNC16(sb + b_dst[it], B + (size_t)(k0 + b_k[it]) * DD + col0 + b_hb[it] * 64 + b_g[it] * 8);
            }
            CP_COMMIT();
        }

        const uint32_t sb = smem_u + (uint32_t)(c % 3) * GSTAGE;
#pragma unroll
        for (int ks = 0; ks < 4; ks++) {
            uint32_t a[4][4], bf[2][4];
            const uint32_t aK = ((uint32_t)(ks * 32) + aSub) ^ swz;
            const uint32_t krow = (uint32_t)(ks * 16) + krow_l;
#pragma unroll
            for (int i = 0; i < 4; i++)
                ldm_x4(a[i], sb + aOff + (uint32_t)i * 2048 + aK);
#pragma unroll
            for (int p = 0; p < 2; p++) {
                const uint32_t g = bGbase + (uint32_t)p * 4 + bg_hi;   // 2a,2a+1 / 2a+4,2a+5
                ldm_x4_t(bf[p], sb + GOFF_B + bHB + krow * 128 + ((g ^ (krow & 7)) * 16));
            }
#pragma unroll
            for (int i = 0; i < 4; i++)
#pragma unroll
                for (int j = 0; j < 4; j++)
                    mma_f16(acc[i][j], a[i], &bf[j >> 1][(j & 1) * 2]);
        }
    }

    // epilogue. col(j) = col0 + (wn>>1)*64 + wa*16 + (j>>1)*32 + (j&1)*8 + qcol
    const int qrow = lane >> 2;
    const int qcol = (lane & 3) * 2;
    const int colbase = col0 + (wn >> 1) * 64 + wa * 16 + qcol;
#pragma unroll
    for (int i = 0; i < 4; i++) {
        const int r0 = row0 + wm * 64 + i * 16 + qrow;
        const int r1 = r0 + 8;

        // bias-added values: v[j][row]
        float2 v[4][2];
#pragma unroll
        for (int j = 0; j < 4; j++) {
            const int col = colbase + (j >> 1) * 32 + (j & 1) * 8;
            float2 bv = *(const float2*)&bias[col];
            v[j][0].x = acc[i][j][0] + bv.x;  v[j][0].y = acc[i][j][1] + bv.y;
            v[j][1].x = acc[i][j][2] + bv.x;  v[j][1].y = acc[i][j][3] + bv.y;
        }

        if (F16OUT) {
            // RoPE for q (z=0, + exp2 scale) and k (z=1); v (z=2) untouched.
            if (z < 2) {
#pragma unroll
                for (int jj = 0; jj < 2; jj++) {
                    const int d = wa * 16 + jj * 8 + qcol;   // even, < 32
#pragma unroll
                    for (int rr = 0; rr < 2; rr++) {
                        const int r = rr ? r1 : r0;
                        const int sI = r & 2047, bI = r >> 11;
                        const float4 cs = rtab4[(((size_t)bI * SS + sI) << 4) + (d >> 1)];
                        float x1 = v[jj][rr].x,     y1 = v[jj][rr].y;
                        float x2 = v[jj + 2][rr].x, y2 = v[jj + 2][rr].y;
                        float nx1 = x1 * cs.x - x2 * cs.y;
                        float nx2 = x2 * cs.x + x1 * cs.y;
                        float ny1 = y1 * cs.z - y2 * cs.w;
                        float ny2 = y2 * cs.z + y1 * cs.w;
                        if (z == 0) { nx1 *= QSCALE; nx2 *= QSCALE; ny1 *= QSCALE; ny2 *= QSCALE; }
                        v[jj][rr].x = nx1;     v[jj][rr].y = ny1;
                        v[jj + 2][rr].x = nx2; v[jj + 2][rr].y = ny2;
                    }
                }
            }
            __half* C = (__half*)Cbase + (size_t)z * MM * DD;
#pragma unroll
            for (int j = 0; j < 4; j++) {
                const int col = colbase + (j >> 1) * 32 + (j & 1) * 8;
                const int hh = col >> 6, dd_ = col & 63;
                const size_t d0 = (((size_t)(r0 >> 11) * HH + hh) * SS + (r0 & 2047)) * HD + dd_;
                const size_t d1 = (((size_t)(r1 >> 11) * HH + hh) * SS + (r1 & 2047)) * HD + dd_;
                *(__half2*)&C[d0] = __floats2half2_rn(v[j][0].x, v[j][0].y);
                *(__half2*)&C[d1] = __floats2half2_rn(v[j][1].x, v[j][1].y);
            }
        } else {
            float* C = (float*)Cbase + (size_t)z * MM * DD;
#pragma unroll
            for (int j = 0; j < 4; j++) {
                const int col = colbase + (j >> 1) * 32 + (j & 1) * 8;
                float2 v0 = v[j][0], v1 = v[j][1];
                if (add != nullptr) {
                    float2 a0 = *(const float2*)&add[(size_t)r0 * DD + col];
                    float2 a1 = *(const float2*)&add[(size_t)r1 * DD + col];
                    v0.x += a0.x; v0.y += a0.y;
                    v1.x += a1.x; v1.y += a1.y;
                }
                *(float2*)&C[(size_t)r0 * DD + col] = v0;
                *(float2*)&C[(size_t)r1 * DD + col] = v1;
            }
        }
    }
}

// ---------------------------------------------------------------------------
// Tensor-core causal flash attention (fp16 mma, fp32 accum, exp2-domain
// online softmax with ex2.approx.f16x2). 64 q-rows x (b,h), 4 warps.
// ---------------------------------------------------------------------------
#define FL_SMEM (5 * 8192)   // Q (8K) + 2 stages x (K 8K + V 8K)

__global__ __launch_bounds__(128)
void flash_mma_kernel(const __half* __restrict__ qg,
                      const __half* __restrict__ kg,
                      const __half* __restrict__ vg,
                      __half* __restrict__ out)
{
    __shared__ __align__(128) char sm[FL_SMEM];
    const uint32_t sQ = smem_to_u32(sm);

    const int b  = blockIdx.z;
    const int h  = blockIdx.y;
    const int q0 = (gridDim.x - 1 - blockIdx.x) * 64;   // big blocks first
    const int tid = threadIdx.x;
    const int wid = tid >> 5;
    const int lane = tid & 31;

    const __half* qptr = qg + (((size_t)b * HH + h) * SS + q0) * HD;
    const __half* kptr = kg + (((size_t)b * HH + h) * SS) * HD;
    const __half* vptr = vg + (((size_t)b * HH + h) * SS) * HD;

#pragma unroll
    for (int it = 0; it < 4; it++) {
        int e = tid + it * 128;
        int r = e >> 3, g = e & 7;
        CP_ASYNC16(sQ + SW128((uint32_t)(r * 128 + g * 16)), (const char*)qptr + e * 16);
    }

    const int ntiles = q0 / 64 + 1;

    {
        const char* ks = (const char*)kptr;
        const char* vs = (const char*)vptr;
        uint32_t base = sQ + 8192;
#pragma unroll
        for (int it = 0; it < 4; it++) {
            int e = tid + it * 128;
            int r = e >> 3, g = e & 7;
            uint32_t d = SW128((uint32_t)(r * 128 + g * 16));
            CP_ASYNC16(base + d, ks + e * 16);
            CP_ASYNC16(base + 8192 + d, vs + e * 16);
        }
        CP_COMMIT();
    }
    if (ntiles > 1) {
        const char* ks = (const char*)(kptr + (size_t)64 * HD);
        const char* vs = (const char*)(vptr + (size_t)64 * HD);
        uint32_t base = sQ + 8192 + 16384;
#pragma unroll
        for (int it = 0; it < 4; it++) {
            int e = tid + it * 128;
            int r = e >> 3, g = e & 7;
            uint32_t d = SW128((uint32_t)(r * 128 + g * 16));
            CP_ASYNC16(base + d, ks + e * 16);
            CP_ASYNC16(base + 8192 + d, vs + e * 16);
        }
        CP_COMMIT();
    }

    const uint32_t swz     = (uint32_t)(lane & 7) * 16;
    const uint32_t qrowoff = (uint32_t)(wid * 16 + (lane & 15)) * 128;
    const uint32_t aSub    = (uint32_t)(lane >> 4) * 16;
    const uint32_t krowoff = (uint32_t)((lane & 7) + ((lane >> 4) ? 8 : 0)) * 128;
    const uint32_t bSub    = (uint32_t)((lane >> 3) & 1) * 16;
    const uint32_t vrow_l  = (uint32_t)(((lane >> 3) & 1) * 8 + (lane & 7));
    const uint32_t vg_hi   = (uint32_t)(lane >> 4);

    float m0 = -1e30f, m1 = -1e30f, l0 = 0.f, l1 = 0.f;
    float o[8][4];
#pragma unroll
    for (int j = 0; j < 8; j++)
#pragma unroll
        for (int u = 0; u < 4; u++) o[j][u] = 0.f;

    const int row_g0 = q0 + wid * 16 + (lane >> 2);
    const int row_g1 = row_g0 + 8;

#pragma unroll 1
    for (int t = 0; t < ntiles; t++) {
        if (t < ntiles - 1) { CP_WAIT_1(); } else { CP_WAIT_0(); }
        __syncthreads();

        const uint32_t kb = sQ + 8192 + (uint32_t)(t & 1) * 16384;
        const uint32_t vb = kb + 8192;

        float s[8][4];
#pragma unroll
        for (int j = 0; j < 8; j++)
#pragma unroll
            for (int u = 0; u < 4; u++) s[j][u] = 0.f;

#pragma unroll
        for (int ks = 0; ks < 4; ks++) {
            uint32_t a[4];
            ldm_x4(a, sQ + qrowoff + (((uint32_t)(ks * 32) + aSub) ^ swz));
#pragma unroll
            for (int nt = 0; nt < 4; nt++) {
                uint32_t bf[4];
                ldm_x4(bf, kb + krowoff + (uint32_t)nt * 2048 +
                            (((uint32_t)(ks * 32) + bSub) ^ swz));
                mma_f16(s[2 * nt],     a, bf);
                mma_f16(s[2 * nt + 1], a, bf + 2);
            }
        }

        if (t == ntiles - 1) {
            const int kbase = t * 64;
#pragma unroll
            for (int j = 0; j < 8; j++) {
                const int col = kbase + j * 8 + (lane & 3) * 2;
                if (col     > row_g0) s[j][0] = -1e30f;
                if (col + 1 > row_g0) s[j][1] = -1e30f;
                if (col     > row_g1) s[j][2] = -1e30f;
                if (col + 1 > row_g1) s[j][3] = -1e30f;
            }
        }

        float x0 = -1e30f, x1 = -1e30f;
#pragma unroll
        for (int j = 0; j < 8; j++) {
            x0 = fmaxf(x0, fmaxf(s[j][0], s[j][1]));
            x1 = fmaxf(x1, fmaxf(s[j][2], s[j][3]));
        }
        x0 = fmaxf(x0, __shfl_xor_sync(0xffffffffu, x0, 1));
        x0 = fmaxf(x0, __shfl_xor_sync(0xffffffffu, x0, 2));
        x1 = fmaxf(x1, __shfl_xor_sync(0xffffffffu, x1, 1));
        x1 = fmaxf(x1, __shfl_xor_sync(0xffffffffu, x1, 2));

        const float mn0 = fmaxf(m0, x0);
        const float mn1 = fmaxf(m1, x1);
        const float a0 = exp2f(m0 - mn0);
        const float a1 = exp2f(m1 - mn1);
        m0 = mn0; m1 = mn1;

        uint32_t pa[4][4];
        float sum0 = 0.f, sum1 = 0.f;
#pragma unroll
        for (int c = 0; c < 4; c++) {
            pa[c][0] = ex2_h2(pack_h2(s[2 * c][0] - mn0,     s[2 * c][1] - mn0));
            pa[c][1] = ex2_h2(pack_h2(s[2 * c][2] - mn1,     s[2 * c][3] - mn1));
            pa[c][2] = ex2_h2(pack_h2(s[2 * c + 1][0] - mn0, s[2 * c + 1][1] - mn0));
            pa[c][3] = ex2_h2(pack_h2(s[2 * c + 1][2] - mn1, s[2 * c + 1][3] - mn1));
            float2 f;
            f = h2_to_f2(pa[c][0]); sum0 += f.x + f.y;
            f = h2_to_f2(pa[c][2]); sum0 += f.x + f.y;
            f = h2_to_f2(pa[c][1]); sum1 += f.x + f.y;
            f = h2_to_f2(pa[c][3]); sum1 += f.x + f.y;
        }
        sum0 += __shfl_xor_sync(0xffffffffu, sum0, 1);
        sum0 += __shfl_xor_sync(0xffffffffu, sum0, 2);
        sum1 += __shfl_xor_sync(0xffffffffu, sum1, 1);
        sum1 += __shfl_xor_sync(0xffffffffu, sum1, 2);
        l0 = l0 * a0 + sum0;
        l1 = l1 * a1 + sum1;

#pragma unroll
        for (int j = 0; j < 8; j++) {
            o[j][0] *= a0; o[j][1] *= a0;
            o[j][2] *= a1; o[j][3] *= a1;
        }

#pragma unroll
        for (int c = 0; c < 4; c++) {
            const uint32_t vrow = (uint32_t)(c * 16) + vrow_l;
#pragma unroll
            for (int nt = 0; nt < 4; nt++) {
                const uint32_t g = (uint32_t)(nt * 2) + vg_hi;
                uint32_t bf[4];
                ldm_x4_t(bf, vb + vrow * 128 + ((g ^ (vrow & 7)) * 16));
                mma_f16(o[2 * nt],     pa[c], bf);
                mma_f16(o[2 * nt + 1], pa[c], bf + 2);
            }
        }

        __syncthreads();

        if (t + 2 < ntiles) {
            const char* ks = (const char*)(kptr + (size_t)(t + 2) * 64 * HD);
            const char* vs = (const char*)(vptr + (size_t)(t + 2) * 64 * HD);
            uint32_t base = sQ + 8192 + (uint32_t)(t & 1) * 16384;
#pragma unroll
            for (int it = 0; it < 4; it++) {
                int e = tid + it * 128;
                int r = e >> 3, g = e & 7;
                uint32_t d = SW128((uint32_t)(r * 128 + g * 16));
                CP_ASYNC16(base + d, ks + e * 16);
                CP_ASYNC16(base + 8192 + d, vs + e * 16);
            }
            CP_COMMIT();
        }
    }

    // write attn out fp16: [b*S + row][h*64 + d]
    const float inv0 = 1.f / l0;
    const float inv1 = 1.f / l1;
    __half* ob = out + ((size_t)b * SS) * DD + h * HD;
#pragma unroll
    for (int j = 0; j < 8; j++) {
        const int col = j * 8 + (lane & 3) * 2;
        *(__half2*)&ob[(size_t)row_g0 * DD + col] = __floats2half2_rn(o[j][0] * inv0, o[j][1] * inv0);
        *(__half2*)&ob[(size_t)row_g1 * DD + col] = __floats2half2_rn(o[j][2] * inv1, o[j][3] * inv1);
    }
}

// ---------------------------------------------------------------------------
// Launch
// ---------------------------------------------------------------------------
extern "C" void kernel_launch(void* const* d_in, const int* in_sizes, int n_in,
                              void* d_out, int out_size)
{
    const float* hidden   = (const float*)d_in[0];
    /* d_in[1] attention_mask: causal tril(0 / -1e9) -> handled analytically */
    const int*   pos_ids  = (const int*)d_in[2];
    const float* qkv_w    = (const float*)d_in[3];
    const float* qkv_b    = (const float*)d_in[4];
    const float* o_w      = (const float*)d_in[5];
    const float* o_b      = (const float*)d_in[6];
    const float* residual = (const float*)d_in[7];
    float*       out      = (float*)d_out;

    void* p = nullptr;
    cudaGetSymbolAddress(&p, g_qkv16);  __half* qkv16 = (__half*)p;
    cudaGetSymbolAddress(&p, g_h16);    __half* h16 = (__half*)p;
    cudaGetSymbolAddress(&p, g_attn16); __half* attn16 = (__half*)p;
    cudaGetSymbolAddress(&p, g_W16);    __half* W16 = (__half*)p;
    cudaGetSymbolAddress(&p, g_rtab);   float4* rtab4 = (float4*)p;

    __half* q16 = qkv16;
    __half* k16 = qkv16 + (size_t)MM * DD;
    __half* v16 = qkv16 + (size_t)2 * MM * DD;

    cudaFuncSetAttribute(gemm_f16_kernel<true>,
                         cudaFuncAttributeMaxDynamicSharedMemorySize, GEMM_SMEM);
    cudaFuncSetAttribute(gemm_f16_kernel<false>,
                         cudaFuncAttributeMaxDynamicSharedMemorySize, GEMM_SMEM);

    // 0) Elementwise fp32->fp16 conversions + rope table
    {
        size_t n2 = (size_t)MM * DD / 2;
        f32_to_f16_kernel<<<(unsigned)(n2 / 256), 256>>>(hidden, h16);
        size_t w2 = (size_t)3 * DD * DD / 2;
        f32_to_f16_kernel<<<(unsigned)(w2 / 256), 256>>>(qkv_w, W16);
        size_t o2 = (size_t)DD * DD / 2;
        f32_to_f16_kernel<<<(unsigned)(o2 / 256), 256>>>(o_w, W16 + (size_t)3 * DD * DD);
        rope_tab_kernel<<<(BB * SS * 32) / 256, 256>>>(pos_ids, (float2*)rtab4);
    }

    // 1) QKV projection -> fp16 head-major [z][b,h,s,d] with fused bias+RoPE
    {
        dim3 grid(DD / 128, MM / 128, 3);
        gemm_f16_kernel<true><<<grid, 256, GEMM_SMEM>>>(h16, W16, qkv_b, nullptr,
                                                        rtab4, qkv16);
    }

    // 2) Tensor-core causal flash attention -> attn16 (fp16)
    {
        dim3 grid(SS / 64, HH, BB);
        flash_mma_kernel<<<grid, 128>>>(q16, k16, v16, attn16);
    }

    // 3) O-projection + bias + residual -> d_out (fp32)
    {
        dim3 grid(DD / 128, MM / 128, 1);
        gemm_f16_kernel<false><<<grid, 256, GEMM_SMEM>>>(attn16, W16 + (size_t)3 * DD * DD,
                                                         o_b, residual, nullptr, out);
    }
}